// round 3
// baseline (speedup 1.0000x reference)
#include <cuda_runtime.h>

#define NWIN  128
#define WSZ   64
#define HD    64
#define SHIFT 32
#define WTOT  8192

__device__ __forceinline__ unsigned long long pk2(float a, float b) {
    unsigned long long r;
    asm("mov.b64 %0, {%1, %2};" : "=l"(r) : "f"(a), "f"(b));
    return r;
}
__device__ __forceinline__ void upk2(unsigned long long x, float &a, float &b) {
    asm("mov.b64 {%0, %1}, %2;" : "=f"(a), "=f"(b) : "l"(x));
}
__device__ __forceinline__ void ffma2(unsigned long long &d, unsigned long long a, unsigned long long b) {
    asm("fma.rn.f32x2 %0, %1, %2, %0;" : "+l"(d) : "l"(a), "l"(b));
}

__global__ __launch_bounds__(256)
void swin_attn_kernel(const float* __restrict__ q,
                      const float* __restrict__ k,
                      const float* __restrict__ v,
                      const float* __restrict__ rel,
                      float* __restrict__ xout,
                      float* __restrict__ aout)
{
    __shared__ float Qt[WSZ * WSZ];   // Qt[kdim][row], pre-scaled by 0.125
    __shared__ float Kt[WSZ * WSZ];   // Kt[kdim][col]
    __shared__ float Vs[WSZ * WSZ];   // Vs[m][c] row-major

    const int t    = threadIdx.x;          // 0..255
    const int blk  = blockIdx.x;           // 0..B*128-1
    const int w    = blk & (NWIN - 1);
    const size_t base = (size_t)(blk >> 7) * (size_t)(WTOT * HD);
    const int wstart = w * WSZ;

    // ---- Global -> smem (roll folded into index), Q/K transposed, V straight ----
    #pragma unroll
    for (int i = 0; i < 4; i++) {
        int idx = t + i * 256;             // 0..1023 float4 slots
        int r   = idx >> 4;                // row in window 0..63
        int c4  = (idx & 15) << 2;         // col 0..60 step 4
        int g   = (wstart + r + SHIFT) & (WTOT - 1);
        size_t off = base + (size_t)g * HD + c4;
        float4 qv = *(const float4*)(q + off);
        float4 kv = *(const float4*)(k + off);
        float4 vv = *(const float4*)(v + off);
        Qt[(c4 + 0) * WSZ + r] = qv.x * 0.125f;
        Qt[(c4 + 1) * WSZ + r] = qv.y * 0.125f;
        Qt[(c4 + 2) * WSZ + r] = qv.z * 0.125f;
        Qt[(c4 + 3) * WSZ + r] = qv.w * 0.125f;
        Kt[(c4 + 0) * WSZ + r] = kv.x;
        Kt[(c4 + 1) * WSZ + r] = kv.y;
        Kt[(c4 + 2) * WSZ + r] = kv.z;
        Kt[(c4 + 3) * WSZ + r] = kv.w;
        *(float4*)(Vs + r * HD + c4) = vv;
    }

    const int tc = t & 15, tr = t >> 4;
    const int c0 = tc << 2, r0 = tr << 2;

    // Relative-position bias: this thread only ever needs n-m in [r0-c0-3, r0-c0+3]
    float bias7[7];
    {
        const int dbase = (r0 - c0) + 60;  // +63 - 3
        #pragma unroll
        for (int d = 0; d < 7; d++) bias7[d] = __ldg(rel + dbase + d);
    }

    __syncthreads();

    // ---- GEMM1: S = (Q*scale) @ K^T  (4x4 tile per thread, packed f32x2 FMA) ----
    unsigned long long acc[4][2] = {};
    #pragma unroll 8
    for (int kk = 0; kk < WSZ; kk++) {
        float4 qv = *(const float4*)(Qt + kk * WSZ + r0);
        float4 kv = *(const float4*)(Kt + kk * WSZ + c0);
        unsigned long long b01 = pk2(kv.x, kv.y);
        unsigned long long b23 = pk2(kv.z, kv.w);
        unsigned long long a0 = pk2(qv.x, qv.x);
        ffma2(acc[0][0], a0, b01); ffma2(acc[0][1], a0, b23);
        unsigned long long a1 = pk2(qv.y, qv.y);
        ffma2(acc[1][0], a1, b01); ffma2(acc[1][1], a1, b23);
        unsigned long long a2 = pk2(qv.z, qv.z);
        ffma2(acc[2][0], a2, b01); ffma2(acc[2][1], a2, b23);
        unsigned long long a3 = pk2(qv.w, qv.w);
        ffma2(acc[3][0], a3, b01); ffma2(acc[3][1], a3, b23);
    }

    float sv[4][4];
    #pragma unroll
    for (int i = 0; i < 4; i++) {
        upk2(acc[i][0], sv[i][0], sv[i][1]);
        upk2(acc[i][1], sv[i][2], sv[i][3]);
    }

    // ---- bias + shift-window mask (only last window is masked) ----
    const bool lastw = (w == NWIN - 1);
    #pragma unroll
    for (int i = 0; i < 4; i++) {
        const int n = r0 + i;
        #pragma unroll
        for (int j = 0; j < 4; j++) {
            const int m = c0 + j;
            float val = sv[i][j] + bias7[i - j + 3];
            if (lastw && ((n >= SHIFT) != (m >= SHIFT))) val -= 100.0f;
            sv[i][j] = val;
        }
    }

    // ---- softmax over each row (16 lanes per row group, lane-aligned) ----
    float inv[4];
    #pragma unroll
    for (int i = 0; i < 4; i++) {
        float mx = fmaxf(fmaxf(sv[i][0], sv[i][1]), fmaxf(sv[i][2], sv[i][3]));
        mx = fmaxf(mx, __shfl_xor_sync(0xffffffffu, mx, 1));
        mx = fmaxf(mx, __shfl_xor_sync(0xffffffffu, mx, 2));
        mx = fmaxf(mx, __shfl_xor_sync(0xffffffffu, mx, 4));
        mx = fmaxf(mx, __shfl_xor_sync(0xffffffffu, mx, 8));
        float e0 = __expf(sv[i][0] - mx);
        float e1 = __expf(sv[i][1] - mx);
        float e2 = __expf(sv[i][2] - mx);
        float e3 = __expf(sv[i][3] - mx);
        sv[i][0] = e0; sv[i][1] = e1; sv[i][2] = e2; sv[i][3] = e3;
        float sum = (e0 + e1) + (e2 + e3);
        sum += __shfl_xor_sync(0xffffffffu, sum, 1);
        sum += __shfl_xor_sync(0xffffffffu, sum, 2);
        sum += __shfl_xor_sync(0xffffffffu, sum, 4);
        sum += __shfl_xor_sync(0xffffffffu, sum, 8);
        inv[i] = __fdividef(1.0f, sum);
    }

    // ---- write attn (global) + P^T into smem (reuse Qt) ----
    __syncthreads();                      // everyone done reading Qt/Kt
    float* Pt = Qt;                       // Pt[m][n]
    const size_t aoff = (size_t)blk * (WSZ * WSZ);
    #pragma unroll
    for (int i = 0; i < 4; i++) {
        float p0 = sv[i][0] * inv[i];
        float p1 = sv[i][1] * inv[i];
        float p2 = sv[i][2] * inv[i];
        float p3 = sv[i][3] * inv[i];
        Pt[(c0 + 0) * WSZ + (r0 + i)] = p0;
        Pt[(c0 + 1) * WSZ + (r0 + i)] = p1;
        Pt[(c0 + 2) * WSZ + (r0 + i)] = p2;
        Pt[(c0 + 3) * WSZ + (r0 + i)] = p3;
        *(float4*)(aout + aoff + (size_t)(r0 + i) * WSZ + c0) = make_float4(p0, p1, p2, p3);
    }
    __syncthreads();

    // ---- GEMM2: O = P @ V ----
    unsigned long long oacc[4][2] = {};
    #pragma unroll 8
    for (int m = 0; m < WSZ; m++) {
        float4 pv = *(const float4*)(Pt + m * WSZ + r0);
        float4 vv = *(const float4*)(Vs + m * HD + c0);
        unsigned long long b01 = pk2(vv.x, vv.y);
        unsigned long long b23 = pk2(vv.z, vv.w);
        unsigned long long a0 = pk2(pv.x, pv.x);
        ffma2(oacc[0][0], a0, b01); ffma2(oacc[0][1], a0, b23);
        unsigned long long a1 = pk2(pv.y, pv.y);
        ffma2(oacc[1][0], a1, b01); ffma2(oacc[1][1], a1, b23);
        unsigned long long a2 = pk2(pv.z, pv.z);
        ffma2(oacc[2][0], a2, b01); ffma2(oacc[2][1], a2, b23);
        unsigned long long a3 = pk2(pv.w, pv.w);
        ffma2(oacc[3][0], a3, b01); ffma2(oacc[3][1], a3, b23);
    }

    #pragma unroll
    for (int i = 0; i < 4; i++) {
        float o0, o1, o2, o3;
        upk2(oacc[i][0], o0, o1);
        upk2(oacc[i][1], o2, o3);
        int g = (wstart + r0 + i + SHIFT) & (WTOT - 1);   // inverse roll == same map
        *(float4*)(xout + base + (size_t)g * HD + c0) = make_float4(o0, o1, o2, o3);
    }
}

extern "C" void kernel_launch(void* const* d_in, const int* in_sizes, int n_in,
                              void* d_out, int out_size) {
    const float* q   = (const float*)d_in[0];
    const float* k   = (const float*)d_in[1];
    const float* v   = (const float*)d_in[2];
    const float* rel = (const float*)d_in[3];

    const int B = in_sizes[0] / (WTOT * HD);      // 32
    float* xout = (float*)d_out;
    float* aout = xout + (size_t)B * WTOT * HD;   // attn follows x

    swin_attn_kernel<<<B * NWIN, 256>>>(q, k, v, rel, xout, aout);
}